// round 3
// baseline (speedup 1.0000x reference)
#include <cuda_runtime.h>

#define NN  100000
#define EE  1600000
#define FIN 128
#define HH  64
#define CC  7

// Scratch (device globals — no allocation allowed)
__device__ __align__(16) float g_p1[NN * HH];
__device__ __align__(16) float g_r1[NN * HH];
__device__ __align__(16) float g_agg1[NN * HH];
__device__ __align__(16) float g_h[NN * HH];
__device__ __align__(16) float g_p2[NN * 8];
__device__ __align__(16) float g_r2[NN * 8];
__device__ __align__(16) float g_agg2[NN * 8];
__device__ float g_deg[NN];

// ---------------------------------------------------------------------------
__global__ void k_zero() {
    int i = blockIdx.x * blockDim.x + threadIdx.x;
    if (i < NN * HH) g_agg1[i] = 0.f;
    if (i < NN * 8)  g_agg2[i] = 0.f;
    if (i < NN)      g_deg[i]  = 0.f;
}

// ---------------------------------------------------------------------------
// GEMM1: p1 = x @ W1l ; r1 = x @ W1r + b1.   x:[n,128], W:[128,64]
// Block: 256 threads, 64 rows/block. smem: Ws[128][128] (W1l|W1r) + Xs[64][128]
__global__ void k_gemm1(const float* __restrict__ x,
                        const float* __restrict__ W1l,
                        const float* __restrict__ W1r,
                        const float* __restrict__ b1, int n) {
    extern __shared__ float sm[];
    float* Ws = sm;                 // 128*128
    float* Xs = sm + FIN * 128;     // 64*128
    int t = threadIdx.x;

    for (int i = t; i < FIN * HH; i += 256) {
        int k = i / HH, c = i % HH;
        Ws[k * 128 + c]      = W1l[i];
        Ws[k * 128 + HH + c] = W1r[i];
    }
    int row0 = blockIdx.x * 64;
    for (int i = t; i < 64 * 32; i += 256) {     // float4 granularity
        int r = i >> 5;
        int row = row0 + r;
        float4 v = make_float4(0.f, 0.f, 0.f, 0.f);
        if (row < n) v = ((const float4*)x)[(long)row * 32 + (i & 31)];
        ((float4*)Xs)[i] = v;
    }
    __syncthreads();

    int tx = t & 15, ty = t >> 4;   // tx: 8-col group (0..15 over 128 cols), ty: 4-row group
    float acc[4][8];
#pragma unroll
    for (int r = 0; r < 4; r++)
#pragma unroll
        for (int j = 0; j < 8; j++) acc[r][j] = 0.f;

#pragma unroll 4
    for (int k = 0; k < FIN; ++k) {
        const float* wr = Ws + k * 128 + tx * 8;
        float4 w0 = *(const float4*)wr;
        float4 w1 = *(const float4*)(wr + 4);
#pragma unroll
        for (int r = 0; r < 4; r++) {
            float xv = Xs[(ty * 4 + r) * FIN + k];
            acc[r][0] += xv * w0.x; acc[r][1] += xv * w0.y;
            acc[r][2] += xv * w0.z; acc[r][3] += xv * w0.w;
            acc[r][4] += xv * w1.x; acc[r][5] += xv * w1.y;
            acc[r][6] += xv * w1.z; acc[r][7] += xv * w1.w;
        }
    }

    bool isR = (tx >= 8);
    int cbase = (tx & 7) * 8;
    float bb[8];
#pragma unroll
    for (int j = 0; j < 8; j++) bb[j] = isR ? __ldg(&b1[cbase + j]) : 0.f;
    float* outbuf = isR ? g_r1 : g_p1;

#pragma unroll
    for (int r = 0; r < 4; r++) {
        int row = row0 + ty * 4 + r;
        if (row < n) {
            float4 o0 = make_float4(acc[r][0] + bb[0], acc[r][1] + bb[1],
                                    acc[r][2] + bb[2], acc[r][3] + bb[3]);
            float4 o1 = make_float4(acc[r][4] + bb[4], acc[r][5] + bb[5],
                                    acc[r][6] + bb[6], acc[r][7] + bb[7]);
            float4* dst = (float4*)(outbuf + (long)row * HH + cbase);
            dst[0] = o0; dst[1] = o1;
        }
    }
}

// ---------------------------------------------------------------------------
// Scatter layer 1: agg1[dst] += p1[src] (64 floats), 16 lanes/edge, vec4 REDG.
__global__ void k_scatter1(const int* __restrict__ ei, int e) {
    int tid = blockIdx.x * blockDim.x + threadIdx.x;
    int ed = tid >> 4, q = tid & 15;
    if (ed >= e) return;
    int src = ei[ed];
    int dst = ei[e + ed];
    float4 v = __ldg(((const float4*)g_p1) + (long)src * 16 + q);
    float4* a = ((float4*)g_agg1) + (long)dst * 16 + q;
    asm volatile("red.global.add.v4.f32 [%0], {%1,%2,%3,%4};"
                 :: "l"(a), "f"(v.x), "f"(v.y), "f"(v.z), "f"(v.w) : "memory");
    if (q == 0) atomicAdd(&g_deg[dst], 1.0f);
}

// ---------------------------------------------------------------------------
// h = relu(agg1/deg + r1)
__global__ void k_h(int n) {
    int i = blockIdx.x * blockDim.x + threadIdx.x;
    if (i >= n * 16) return;
    int node = i >> 4;
    float invd = 1.0f / fmaxf(g_deg[node], 1.0f);
    float4 a = ((const float4*)g_agg1)[i];
    float4 r = ((const float4*)g_r1)[i];
    float4 o;
    o.x = fmaxf(a.x * invd + r.x, 0.f);
    o.y = fmaxf(a.y * invd + r.y, 0.f);
    o.z = fmaxf(a.z * invd + r.z, 0.f);
    o.w = fmaxf(a.w * invd + r.w, 0.f);
    ((float4*)g_h)[i] = o;
}

// ---------------------------------------------------------------------------
// GEMM2: p2 = h @ W2l (pad to 8), r2 = h @ W2r + b2 (pad to 8).
// 128 threads/block, 128 nodes/block, h staged in padded smem.
__global__ void k_gemm2(const float* __restrict__ W2l,
                        const float* __restrict__ W2r,
                        const float* __restrict__ b2, int n) {
    __shared__ float hs[128 * 65];
    __shared__ float Wc[64 * 16];   // cols 0..6 = W2l, 8..14 = W2r, 7/15 = 0
    int t = threadIdx.x;
    int node0 = blockIdx.x * 128;

    for (int i = t; i < 64 * 16; i += 128) {
        int k = i >> 4, c = i & 15;
        float v = 0.f;
        if ((c & 7) < 7) v = (c < 8) ? W2l[k * 7 + c] : W2r[k * 7 + (c - 8)];
        Wc[i] = v;
    }
    for (int idx = t; idx < 128 * 64; idx += 128) {
        int row = idx >> 6, k = idx & 63;
        int node = node0 + row;
        hs[row * 65 + k] = (node < n) ? g_h[(long)node * 64 + k] : 0.f;
    }
    __syncthreads();

    int node = node0 + t;
    if (node >= n) return;

    float al[8], ar[8];
#pragma unroll
    for (int j = 0; j < 8; j++) { al[j] = 0.f; ar[j] = 0.f; }

#pragma unroll 4
    for (int k = 0; k < 64; ++k) {
        float hv = hs[t * 65 + k];
        const float* wr = Wc + k * 16;
        float4 a = *(const float4*)(wr);
        float4 b = *(const float4*)(wr + 4);
        float4 c = *(const float4*)(wr + 8);
        float4 d = *(const float4*)(wr + 12);
        al[0] += hv * a.x; al[1] += hv * a.y; al[2] += hv * a.z; al[3] += hv * a.w;
        al[4] += hv * b.x; al[5] += hv * b.y; al[6] += hv * b.z; al[7] += hv * b.w;
        ar[0] += hv * c.x; ar[1] += hv * c.y; ar[2] += hv * c.z; ar[3] += hv * c.w;
        ar[4] += hv * d.x; ar[5] += hv * d.y; ar[6] += hv * d.z; ar[7] += hv * d.w;
    }

    float bz[8];
#pragma unroll
    for (int c = 0; c < 7; c++) bz[c] = __ldg(&b2[c]);
    bz[7] = 0.f;

    float4* p2o = (float4*)(g_p2 + (long)node * 8);
    p2o[0] = make_float4(al[0], al[1], al[2], al[3]);
    p2o[1] = make_float4(al[4], al[5], al[6], 0.f);
    float4* r2o = (float4*)(g_r2 + (long)node * 8);
    r2o[0] = make_float4(ar[0] + bz[0], ar[1] + bz[1], ar[2] + bz[2], ar[3] + bz[3]);
    r2o[1] = make_float4(ar[4] + bz[4], ar[5] + bz[5], ar[6] + bz[6], 0.f);
}

// ---------------------------------------------------------------------------
// Scatter layer 2: agg2[dst] += p2[src] (8 floats), 2 lanes/edge.
__global__ void k_scatter2(const int* __restrict__ ei, int e) {
    int tid = blockIdx.x * blockDim.x + threadIdx.x;
    int ed = tid >> 1, q = tid & 1;
    if (ed >= e) return;
    int src = ei[ed];
    int dst = ei[e + ed];
    float4 v = __ldg(((const float4*)g_p2) + (long)src * 2 + q);
    float4* a = ((float4*)g_agg2) + (long)dst * 2 + q;
    asm volatile("red.global.add.v4.f32 [%0], {%1,%2,%3,%4};"
                 :: "l"(a), "f"(v.x), "f"(v.y), "f"(v.z), "f"(v.w) : "memory");
}

// ---------------------------------------------------------------------------
// out = log_softmax(agg2/deg + r2)
__global__ void k_final(float* __restrict__ out, int n) {
    int node = blockIdx.x * blockDim.x + threadIdx.x;
    if (node >= n) return;
    float invd = 1.0f / fmaxf(g_deg[node], 1.0f);
    float4 a0 = ((const float4*)g_agg2)[(long)node * 2];
    float4 a1 = ((const float4*)g_agg2)[(long)node * 2 + 1];
    float4 r0 = ((const float4*)g_r2)[(long)node * 2];
    float4 r1 = ((const float4*)g_r2)[(long)node * 2 + 1];
    float v[7];
    v[0] = a0.x * invd + r0.x;
    v[1] = a0.y * invd + r0.y;
    v[2] = a0.z * invd + r0.z;
    v[3] = a0.w * invd + r0.w;
    v[4] = a1.x * invd + r1.x;
    v[5] = a1.y * invd + r1.y;
    v[6] = a1.z * invd + r1.z;
    float m = v[0];
#pragma unroll
    for (int c = 1; c < 7; c++) m = fmaxf(m, v[c]);
    float s = 0.f;
#pragma unroll
    for (int c = 0; c < 7; c++) s += expf(v[c] - m);
    float lse = m + logf(s);
#pragma unroll
    for (int c = 0; c < 7; c++) out[(long)node * 7 + c] = v[c] - lse;
}

// ---------------------------------------------------------------------------
extern "C" void kernel_launch(void* const* d_in, const int* in_sizes, int n_in,
                              void* d_out, int out_size) {
    const float* x   = (const float*)d_in[0];
    const int*   ei  = (const int*)d_in[1];
    const float* W1l = (const float*)d_in[2];
    const float* W1r = (const float*)d_in[3];
    const float* b1  = (const float*)d_in[4];
    const float* W2l = (const float*)d_in[5];
    const float* W2r = (const float*)d_in[6];
    const float* b2  = (const float*)d_in[7];
    float* out = (float*)d_out;

    int n = in_sizes[0] / FIN;
    int e = in_sizes[1] / 2;
    if (n > NN) n = NN;
    if (e > EE) e = EE;

    // 96 KB dynamic smem for gemm1 (attribute set executes immediately;
    // host-side, replays don't re-run this)
    cudaFuncSetAttribute(k_gemm1, cudaFuncAttributeMaxDynamicSharedMemorySize,
                         (FIN * 128 + 64 * FIN) * (int)sizeof(float));

    k_zero<<<(NN * HH + 255) / 256, 256>>>();
    k_gemm1<<<(n + 63) / 64, 256, (FIN * 128 + 64 * FIN) * sizeof(float)>>>(
        x, W1l, W1r, b1, n);
    long st1 = (long)e * 16;
    k_scatter1<<<(int)((st1 + 255) / 256), 256>>>(ei, e);
    k_h<<<(n * 16 + 255) / 256, 256>>>(n);
    k_gemm2<<<(n + 127) / 128, 128>>>(W2l, W2r, b2, n);
    k_scatter2<<<(e * 2 + 255) / 256, 256>>>(ei, e);
    k_final<<<(n + 255) / 256, 256>>>(out, n);
}

// round 5
// speedup vs baseline: 1.0022x; 1.0022x over previous
#include <cuda_runtime.h>

#define NN  100000
#define EE  1600000
#define FIN 128
#define HH  64
#define CC  7

// Scratch (device globals — no allocation allowed)
__device__ __align__(16) float g_p1[NN * HH];
__device__ __align__(16) float g_r1[NN * HH];
__device__ __align__(16) float g_agg1[NN * HH];
__device__ __align__(16) float g_h[NN * HH];
__device__ __align__(16) float g_p2[NN * 8];
__device__ __align__(16) float g_r2[NN * 8];
__device__ __align__(16) float g_agg2[NN * 8];
__device__ float g_deg[NN];

// ---------------------------------------------------------------------------
__global__ void k_zero() {
    int i = blockIdx.x * blockDim.x + threadIdx.x;
    if (i < NN * HH) g_agg1[i] = 0.f;
    if (i < NN * 8)  g_agg2[i] = 0.f;
    if (i < NN)      g_deg[i]  = 0.f;
}

// ---------------------------------------------------------------------------
// GEMM1: p1 = x @ W1l ; r1 = x @ W1r + b1.   x:[n,128], W:[128,64]
// Block: 256 threads, 64 rows/block. smem: Ws[128][128] (W1l|W1r) + Xs[64][128]
__global__ void k_gemm1(const float* __restrict__ x,
                        const float* __restrict__ W1l,
                        const float* __restrict__ W1r,
                        const float* __restrict__ b1, int n) {
    extern __shared__ float sm[];
    float* Ws = sm;                 // 128*128
    float* Xs = sm + FIN * 128;     // 64*128
    int t = threadIdx.x;

    for (int i = t; i < FIN * HH; i += 256) {
        int k = i / HH, c = i % HH;
        Ws[k * 128 + c]      = W1l[i];
        Ws[k * 128 + HH + c] = W1r[i];
    }
    int row0 = blockIdx.x * 64;
    for (int i = t; i < 64 * 32; i += 256) {     // float4 granularity
        int r = i >> 5;
        int row = row0 + r;
        float4 v = make_float4(0.f, 0.f, 0.f, 0.f);
        if (row < n) v = ((const float4*)x)[(long)row * 32 + (i & 31)];
        ((float4*)Xs)[i] = v;
    }
    __syncthreads();

    int tx = t & 15, ty = t >> 4;   // tx: 8-col group (0..15 over 128 cols), ty: 4-row group
    float acc[4][8];
#pragma unroll
    for (int r = 0; r < 4; r++)
#pragma unroll
        for (int j = 0; j < 8; j++) acc[r][j] = 0.f;

#pragma unroll 4
    for (int k = 0; k < FIN; ++k) {
        const float* wr = Ws + k * 128 + tx * 8;
        float4 w0 = *(const float4*)wr;
        float4 w1 = *(const float4*)(wr + 4);
#pragma unroll
        for (int r = 0; r < 4; r++) {
            float xv = Xs[(ty * 4 + r) * FIN + k];
            acc[r][0] += xv * w0.x; acc[r][1] += xv * w0.y;
            acc[r][2] += xv * w0.z; acc[r][3] += xv * w0.w;
            acc[r][4] += xv * w1.x; acc[r][5] += xv * w1.y;
            acc[r][6] += xv * w1.z; acc[r][7] += xv * w1.w;
        }
    }

    bool isR = (tx >= 8);
    int cbase = (tx & 7) * 8;
    float bb[8];
#pragma unroll
    for (int j = 0; j < 8; j++) bb[j] = isR ? __ldg(&b1[cbase + j]) : 0.f;
    float* outbuf = isR ? g_r1 : g_p1;

#pragma unroll
    for (int r = 0; r < 4; r++) {
        int row = row0 + ty * 4 + r;
        if (row < n) {
            float4 o0 = make_float4(acc[r][0] + bb[0], acc[r][1] + bb[1],
                                    acc[r][2] + bb[2], acc[r][3] + bb[3]);
            float4 o1 = make_float4(acc[r][4] + bb[4], acc[r][5] + bb[5],
                                    acc[r][6] + bb[6], acc[r][7] + bb[7]);
            float4* dst = (float4*)(outbuf + (long)row * HH + cbase);
            dst[0] = o0; dst[1] = o1;
        }
    }
}

// ---------------------------------------------------------------------------
// Scatter layer 1: agg1[dst] += p1[src] (64 floats), 16 lanes/edge, vec4 REDG.
__global__ void k_scatter1(const int* __restrict__ ei, int e) {
    int tid = blockIdx.x * blockDim.x + threadIdx.x;
    int ed = tid >> 4, q = tid & 15;
    if (ed >= e) return;
    int src = ei[ed];
    int dst = ei[e + ed];
    float4 v = __ldg(((const float4*)g_p1) + (long)src * 16 + q);
    float4* a = ((float4*)g_agg1) + (long)dst * 16 + q;
    asm volatile("red.global.add.v4.f32 [%0], {%1,%2,%3,%4};"
                 :: "l"(a), "f"(v.x), "f"(v.y), "f"(v.z), "f"(v.w) : "memory");
    if (q == 0) atomicAdd(&g_deg[dst], 1.0f);
}

// ---------------------------------------------------------------------------
// h = relu(agg1/deg + r1)
__global__ void k_h(int n) {
    int i = blockIdx.x * blockDim.x + threadIdx.x;
    if (i >= n * 16) return;
    int node = i >> 4;
    float invd = 1.0f / fmaxf(g_deg[node], 1.0f);
    float4 a = ((const float4*)g_agg1)[i];
    float4 r = ((const float4*)g_r1)[i];
    float4 o;
    o.x = fmaxf(a.x * invd + r.x, 0.f);
    o.y = fmaxf(a.y * invd + r.y, 0.f);
    o.z = fmaxf(a.z * invd + r.z, 0.f);
    o.w = fmaxf(a.w * invd + r.w, 0.f);
    ((float4*)g_h)[i] = o;
}

// ---------------------------------------------------------------------------
// GEMM2: p2 = h @ W2l (pad to 8), r2 = h @ W2r + b2 (pad to 8).
// 128 threads/block, 128 nodes/block, h staged in padded smem.
__global__ void k_gemm2(const float* __restrict__ W2l,
                        const float* __restrict__ W2r,
                        const float* __restrict__ b2, int n) {
    __shared__ float hs[128 * 65];
    __shared__ float Wc[64 * 16];   // cols 0..6 = W2l, 8..14 = W2r, 7/15 = 0
    int t = threadIdx.x;
    int node0 = blockIdx.x * 128;

    for (int i = t; i < 64 * 16; i += 128) {
        int k = i >> 4, c = i & 15;
        float v = 0.f;
        if ((c & 7) < 7) v = (c < 8) ? W2l[k * 7 + c] : W2r[k * 7 + (c - 8)];
        Wc[i] = v;
    }
    for (int idx = t; idx < 128 * 64; idx += 128) {
        int row = idx >> 6, k = idx & 63;
        int node = node0 + row;
        hs[row * 65 + k] = (node < n) ? g_h[(long)node * 64 + k] : 0.f;
    }
    __syncthreads();

    int node = node0 + t;
    if (node >= n) return;

    float al[8], ar[8];
#pragma unroll
    for (int j = 0; j < 8; j++) { al[j] = 0.f; ar[j] = 0.f; }

#pragma unroll 4
    for (int k = 0; k < 64; ++k) {
        float hv = hs[t * 65 + k];
        const float* wr = Wc + k * 16;
        float4 a = *(const float4*)(wr);
        float4 b = *(const float4*)(wr + 4);
        float4 c = *(const float4*)(wr + 8);
        float4 d = *(const float4*)(wr + 12);
        al[0] += hv * a.x; al[1] += hv * a.y; al[2] += hv * a.z; al[3] += hv * a.w;
        al[4] += hv * b.x; al[5] += hv * b.y; al[6] += hv * b.z; al[7] += hv * b.w;
        ar[0] += hv * c.x; ar[1] += hv * c.y; ar[2] += hv * c.z; ar[3] += hv * c.w;
        ar[4] += hv * d.x; ar[5] += hv * d.y; ar[6] += hv * d.z; ar[7] += hv * d.w;
    }

    float bz[8];
#pragma unroll
    for (int c = 0; c < 7; c++) bz[c] = __ldg(&b2[c]);
    bz[7] = 0.f;

    float4* p2o = (float4*)(g_p2 + (long)node * 8);
    p2o[0] = make_float4(al[0], al[1], al[2], al[3]);
    p2o[1] = make_float4(al[4], al[5], al[6], 0.f);
    float4* r2o = (float4*)(g_r2 + (long)node * 8);
    r2o[0] = make_float4(ar[0] + bz[0], ar[1] + bz[1], ar[2] + bz[2], ar[3] + bz[3]);
    r2o[1] = make_float4(ar[4] + bz[4], ar[5] + bz[5], ar[6] + bz[6], 0.f);
}

// ---------------------------------------------------------------------------
// Scatter layer 2: agg2[dst] += p2[src] (8 floats), 2 lanes/edge.
__global__ void k_scatter2(const int* __restrict__ ei, int e) {
    int tid = blockIdx.x * blockDim.x + threadIdx.x;
    int ed = tid >> 1, q = tid & 1;
    if (ed >= e) return;
    int src = ei[ed];
    int dst = ei[e + ed];
    float4 v = __ldg(((const float4*)g_p2) + (long)src * 2 + q);
    float4* a = ((float4*)g_agg2) + (long)dst * 2 + q;
    asm volatile("red.global.add.v4.f32 [%0], {%1,%2,%3,%4};"
                 :: "l"(a), "f"(v.x), "f"(v.y), "f"(v.z), "f"(v.w) : "memory");
}

// ---------------------------------------------------------------------------
// out = log_softmax(agg2/deg + r2)
__global__ void k_final(float* __restrict__ out, int n) {
    int node = blockIdx.x * blockDim.x + threadIdx.x;
    if (node >= n) return;
    float invd = 1.0f / fmaxf(g_deg[node], 1.0f);
    float4 a0 = ((const float4*)g_agg2)[(long)node * 2];
    float4 a1 = ((const float4*)g_agg2)[(long)node * 2 + 1];
    float4 r0 = ((const float4*)g_r2)[(long)node * 2];
    float4 r1 = ((const float4*)g_r2)[(long)node * 2 + 1];
    float v[7];
    v[0] = a0.x * invd + r0.x;
    v[1] = a0.y * invd + r0.y;
    v[2] = a0.z * invd + r0.z;
    v[3] = a0.w * invd + r0.w;
    v[4] = a1.x * invd + r1.x;
    v[5] = a1.y * invd + r1.y;
    v[6] = a1.z * invd + r1.z;
    float m = v[0];
#pragma unroll
    for (int c = 1; c < 7; c++) m = fmaxf(m, v[c]);
    float s = 0.f;
#pragma unroll
    for (int c = 0; c < 7; c++) s += expf(v[c] - m);
    float lse = m + logf(s);
#pragma unroll
    for (int c = 0; c < 7; c++) out[(long)node * 7 + c] = v[c] - lse;
}

// ---------------------------------------------------------------------------
extern "C" void kernel_launch(void* const* d_in, const int* in_sizes, int n_in,
                              void* d_out, int out_size) {
    const float* x   = (const float*)d_in[0];
    const int*   ei  = (const int*)d_in[1];
    const float* W1l = (const float*)d_in[2];
    const float* W1r = (const float*)d_in[3];
    const float* b1  = (const float*)d_in[4];
    const float* W2l = (const float*)d_in[5];
    const float* W2r = (const float*)d_in[6];
    const float* b2  = (const float*)d_in[7];
    float* out = (float*)d_out;

    int n = in_sizes[0] / FIN;
    int e = in_sizes[1] / 2;
    if (n > NN) n = NN;
    if (e > EE) e = EE;

    // 96 KB dynamic smem for gemm1 (attribute set executes immediately;
    // host-side, replays don't re-run this)
    cudaFuncSetAttribute(k_gemm1, cudaFuncAttributeMaxDynamicSharedMemorySize,
                         (FIN * 128 + 64 * FIN) * (int)sizeof(float));

    k_zero<<<(NN * HH + 255) / 256, 256>>>();
    k_gemm1<<<(n + 63) / 64, 256, (FIN * 128 + 64 * FIN) * sizeof(float)>>>(
        x, W1l, W1r, b1, n);
    long st1 = (long)e * 16;
    k_scatter1<<<(int)((st1 + 255) / 256), 256>>>(ei, e);
    k_h<<<(n * 16 + 255) / 256, 256>>>(n);
    k_gemm2<<<(n + 127) / 128, 128>>>(W2l, W2r, b2, n);
    k_scatter2<<<(e * 2 + 255) / 256, 256>>>(ei, e);
    k_final<<<(n + 255) / 256, 256>>>(out, n);
}

// round 6
// speedup vs baseline: 1.1894x; 1.1868x over previous
#include <cuda_runtime.h>

#define NN  100000
#define EE  1600000
#define FIN 128
#define HH  64
#define CC  7
#define NBLK 391   // ceil(NN/256)

// Scratch (device globals — no allocation allowed)
__device__ __align__(16) float g_p1[NN * HH];
__device__ __align__(16) float g_r1[NN * HH];
__device__ __align__(16) float g_h[NN * HH];
__device__ __align__(16) float g_p2[NN * 8];
__device__ __align__(16) float g_r2[NN * 8];
// CSR build
__device__ int g_degi[NN];
__device__ int g_incl[NN];
__device__ int g_rowstart[NN];
__device__ int g_cursor[NN];
__device__ int g_bsum[512];
__device__ int g_boff[512];
__device__ int g_csr[EE];

// ---------------------------------------------------------------------------
__global__ void k_zero_deg() {
    int i = blockIdx.x * blockDim.x + threadIdx.x;
    if (i < NN) g_degi[i] = 0;
}

// histogram of dst
__global__ void k_hist(const int* __restrict__ ei, int e) {
    int i = blockIdx.x * blockDim.x + threadIdx.x;
    if (i < e) atomicAdd(&g_degi[ei[e + i]], 1);
}

// per-block inclusive scan (256 elems/block)
__global__ void k_scan1(int n) {
    __shared__ int s[256];
    int i = blockIdx.x * 256 + threadIdx.x;
    int v = (i < n) ? g_degi[i] : 0;
    s[threadIdx.x] = v;
    __syncthreads();
#pragma unroll
    for (int off = 1; off < 256; off <<= 1) {
        int t = (threadIdx.x >= off) ? s[threadIdx.x - off] : 0;
        __syncthreads();
        s[threadIdx.x] += t;
        __syncthreads();
    }
    if (i < n) g_incl[i] = s[threadIdx.x];
    if (threadIdx.x == 255) g_bsum[blockIdx.x] = s[255];
}

// scan of block sums (single block, 512 threads covers 391 blocks)
__global__ void k_scan2() {
    __shared__ int s[512];
    int t = threadIdx.x;
    int v = (t < NBLK) ? g_bsum[t] : 0;
    s[t] = v;
    __syncthreads();
#pragma unroll
    for (int off = 1; off < 512; off <<= 1) {
        int u = (t >= off) ? s[t - off] : 0;
        __syncthreads();
        s[t] += u;
        __syncthreads();
    }
    if (t < NBLK) g_boff[t] = s[t] - v;   // exclusive
}

// row starts + cursors
__global__ void k_scan3(int n) {
    int i = blockIdx.x * blockDim.x + threadIdx.x;
    if (i >= n) return;
    int start = g_incl[i] - g_degi[i] + g_boff[i >> 8];
    g_rowstart[i] = start;
    g_cursor[i] = start;
}

// fill CSR: csr[pos] = src, grouped by dst
__global__ void k_fill(const int* __restrict__ ei, int e) {
    int i = blockIdx.x * blockDim.x + threadIdx.x;
    if (i >= e) return;
    int src = ei[i];
    int dst = ei[e + i];
    int pos = atomicAdd(&g_cursor[dst], 1);
    g_csr[pos] = src;
}

// ---------------------------------------------------------------------------
// GEMM1: p1 = x @ W1l ; r1 = x @ W1r + b1.   x:[n,128], W:[128,64]
__global__ void k_gemm1(const float* __restrict__ x,
                        const float* __restrict__ W1l,
                        const float* __restrict__ W1r,
                        const float* __restrict__ b1, int n) {
    extern __shared__ float sm[];
    float* Ws = sm;                 // 128*128
    float* Xs = sm + FIN * 128;     // 64*128
    int t = threadIdx.x;

    for (int i = t; i < FIN * HH; i += 256) {
        int k = i / HH, c = i % HH;
        Ws[k * 128 + c]      = W1l[i];
        Ws[k * 128 + HH + c] = W1r[i];
    }
    int row0 = blockIdx.x * 64;
    for (int i = t; i < 64 * 32; i += 256) {
        int r = i >> 5;
        int row = row0 + r;
        float4 v = make_float4(0.f, 0.f, 0.f, 0.f);
        if (row < n) v = ((const float4*)x)[(long)row * 32 + (i & 31)];
        ((float4*)Xs)[i] = v;
    }
    __syncthreads();

    int tx = t & 15, ty = t >> 4;
    float acc[4][8];
#pragma unroll
    for (int r = 0; r < 4; r++)
#pragma unroll
        for (int j = 0; j < 8; j++) acc[r][j] = 0.f;

#pragma unroll 4
    for (int k = 0; k < FIN; ++k) {
        const float* wr = Ws + k * 128 + tx * 8;
        float4 w0 = *(const float4*)wr;
        float4 w1 = *(const float4*)(wr + 4);
#pragma unroll
        for (int r = 0; r < 4; r++) {
            float xv = Xs[(ty * 4 + r) * FIN + k];
            acc[r][0] += xv * w0.x; acc[r][1] += xv * w0.y;
            acc[r][2] += xv * w0.z; acc[r][3] += xv * w0.w;
            acc[r][4] += xv * w1.x; acc[r][5] += xv * w1.y;
            acc[r][6] += xv * w1.z; acc[r][7] += xv * w1.w;
        }
    }

    bool isR = (tx >= 8);
    int cbase = (tx & 7) * 8;
    float bb[8];
#pragma unroll
    for (int j = 0; j < 8; j++) bb[j] = isR ? __ldg(&b1[cbase + j]) : 0.f;
    float* outbuf = isR ? g_r1 : g_p1;

#pragma unroll
    for (int r = 0; r < 4; r++) {
        int row = row0 + ty * 4 + r;
        if (row < n) {
            float4 o0 = make_float4(acc[r][0] + bb[0], acc[r][1] + bb[1],
                                    acc[r][2] + bb[2], acc[r][3] + bb[3]);
            float4 o1 = make_float4(acc[r][4] + bb[4], acc[r][5] + bb[5],
                                    acc[r][6] + bb[6], acc[r][7] + bb[7]);
            float4* dst = (float4*)(outbuf + (long)row * HH + cbase);
            dst[0] = o0; dst[1] = o1;
        }
    }
}

// ---------------------------------------------------------------------------
// Fused layer-1 aggregation: h = relu(mean_{src in N(dst)} p1[src] + r1[dst])
// 16 lanes per node, each lane owns one float4 column chunk.
__global__ void k_agg1(int n) {
    int tid = blockIdx.x * blockDim.x + threadIdx.x;
    int node = tid >> 4, q = tid & 15;
    if (node >= n) return;
    int start = g_rowstart[node];
    int d = g_degi[node];
    const float4* p1 = (const float4*)g_p1;
    float4 acc = make_float4(0.f, 0.f, 0.f, 0.f);
    int j = 0;
    for (; j + 2 <= d; j += 2) {
        int s0 = __ldg(&g_csr[start + j]);
        int s1 = __ldg(&g_csr[start + j + 1]);
        float4 v0 = __ldg(p1 + (long)s0 * 16 + q);
        float4 v1 = __ldg(p1 + (long)s1 * 16 + q);
        acc.x += v0.x + v1.x; acc.y += v0.y + v1.y;
        acc.z += v0.z + v1.z; acc.w += v0.w + v1.w;
    }
    if (j < d) {
        int s0 = __ldg(&g_csr[start + j]);
        float4 v0 = __ldg(p1 + (long)s0 * 16 + q);
        acc.x += v0.x; acc.y += v0.y; acc.z += v0.z; acc.w += v0.w;
    }
    float invd = 1.0f / fmaxf((float)d, 1.0f);
    float4 r = ((const float4*)g_r1)[(long)node * 16 + q];
    float4 o;
    o.x = fmaxf(acc.x * invd + r.x, 0.f);
    o.y = fmaxf(acc.y * invd + r.y, 0.f);
    o.z = fmaxf(acc.z * invd + r.z, 0.f);
    o.w = fmaxf(acc.w * invd + r.w, 0.f);
    ((float4*)g_h)[(long)node * 16 + q] = o;
}

// ---------------------------------------------------------------------------
// GEMM2: p2 = h @ W2l (pad 8), r2 = h @ W2r + b2 (pad 8)
__global__ void k_gemm2(const float* __restrict__ W2l,
                        const float* __restrict__ W2r,
                        const float* __restrict__ b2, int n) {
    __shared__ float hs[128 * 65];
    __shared__ float Wc[64 * 16];
    int t = threadIdx.x;
    int node0 = blockIdx.x * 128;

    for (int i = t; i < 64 * 16; i += 128) {
        int k = i >> 4, c = i & 15;
        float v = 0.f;
        if ((c & 7) < 7) v = (c < 8) ? W2l[k * 7 + c] : W2r[k * 7 + (c - 8)];
        Wc[i] = v;
    }
    for (int idx = t; idx < 128 * 64; idx += 128) {
        int row = idx >> 6, k = idx & 63;
        int node = node0 + row;
        hs[row * 65 + k] = (node < n) ? g_h[(long)node * 64 + k] : 0.f;
    }
    __syncthreads();

    int node = node0 + t;
    if (node >= n) return;

    float al[8], ar[8];
#pragma unroll
    for (int j = 0; j < 8; j++) { al[j] = 0.f; ar[j] = 0.f; }

#pragma unroll 4
    for (int k = 0; k < 64; ++k) {
        float hv = hs[t * 65 + k];
        const float* wr = Wc + k * 16;
        float4 a = *(const float4*)(wr);
        float4 b = *(const float4*)(wr + 4);
        float4 c = *(const float4*)(wr + 8);
        float4 d = *(const float4*)(wr + 12);
        al[0] += hv * a.x; al[1] += hv * a.y; al[2] += hv * a.z; al[3] += hv * a.w;
        al[4] += hv * b.x; al[5] += hv * b.y; al[6] += hv * b.z; al[7] += hv * b.w;
        ar[0] += hv * c.x; ar[1] += hv * c.y; ar[2] += hv * c.z; ar[3] += hv * c.w;
        ar[4] += hv * d.x; ar[5] += hv * d.y; ar[6] += hv * d.z; ar[7] += hv * d.w;
    }

    float bz[7];
#pragma unroll
    for (int c = 0; c < 7; c++) bz[c] = __ldg(&b2[c]);

    float4* p2o = (float4*)(g_p2 + (long)node * 8);
    p2o[0] = make_float4(al[0], al[1], al[2], al[3]);
    p2o[1] = make_float4(al[4], al[5], al[6], 0.f);
    float4* r2o = (float4*)(g_r2 + (long)node * 8);
    r2o[0] = make_float4(ar[0] + bz[0], ar[1] + bz[1], ar[2] + bz[2], ar[3] + bz[3]);
    r2o[1] = make_float4(ar[4] + bz[4], ar[5] + bz[5], ar[6] + bz[6], 0.f);
}

// ---------------------------------------------------------------------------
// Fused layer-2 aggregation + log_softmax: one thread per node.
__global__ void k_agg2(float* __restrict__ out, int n) {
    int node = blockIdx.x * blockDim.x + threadIdx.x;
    if (node >= n) return;
    int start = g_rowstart[node];
    int d = g_degi[node];
    const float4* p2 = (const float4*)g_p2;
    float4 a0 = make_float4(0.f, 0.f, 0.f, 0.f);
    float4 a1 = make_float4(0.f, 0.f, 0.f, 0.f);
    for (int j = 0; j < d; j++) {
        int s = __ldg(&g_csr[start + j]);
        float4 v0 = __ldg(p2 + (long)s * 2);
        float4 v1 = __ldg(p2 + (long)s * 2 + 1);
        a0.x += v0.x; a0.y += v0.y; a0.z += v0.z; a0.w += v0.w;
        a1.x += v1.x; a1.y += v1.y; a1.z += v1.z;
    }
    float invd = 1.0f / fmaxf((float)d, 1.0f);
    float4 r0 = ((const float4*)g_r2)[(long)node * 2];
    float4 r1 = ((const float4*)g_r2)[(long)node * 2 + 1];
    float v[7];
    v[0] = a0.x * invd + r0.x;
    v[1] = a0.y * invd + r0.y;
    v[2] = a0.z * invd + r0.z;
    v[3] = a0.w * invd + r0.w;
    v[4] = a1.x * invd + r1.x;
    v[5] = a1.y * invd + r1.y;
    v[6] = a1.z * invd + r1.z;
    float m = v[0];
#pragma unroll
    for (int c = 1; c < 7; c++) m = fmaxf(m, v[c]);
    float s = 0.f;
#pragma unroll
    for (int c = 0; c < 7; c++) s += expf(v[c] - m);
    float lse = m + logf(s);
#pragma unroll
    for (int c = 0; c < 7; c++) out[(long)node * 7 + c] = v[c] - lse;
}

// ---------------------------------------------------------------------------
extern "C" void kernel_launch(void* const* d_in, const int* in_sizes, int n_in,
                              void* d_out, int out_size) {
    const float* x   = (const float*)d_in[0];
    const int*   ei  = (const int*)d_in[1];
    const float* W1l = (const float*)d_in[2];
    const float* W1r = (const float*)d_in[3];
    const float* b1  = (const float*)d_in[4];
    const float* W2l = (const float*)d_in[5];
    const float* W2r = (const float*)d_in[6];
    const float* b2  = (const float*)d_in[7];
    float* out = (float*)d_out;

    int n = in_sizes[0] / FIN;
    int e = in_sizes[1] / 2;
    if (n > NN) n = NN;
    if (e > EE) e = EE;

    cudaFuncSetAttribute(k_gemm1, cudaFuncAttributeMaxDynamicSharedMemorySize,
                         (FIN * 128 + 64 * FIN) * (int)sizeof(float));

    // CSR build
    k_zero_deg<<<NBLK, 256>>>();
    k_hist<<<(e + 255) / 256, 256>>>(ei, e);
    k_scan1<<<NBLK, 256>>>(n);
    k_scan2<<<1, 512>>>();
    k_scan3<<<NBLK, 256>>>(n);
    k_fill<<<(e + 255) / 256, 256>>>(ei, e);

    // Layer 1
    k_gemm1<<<(n + 63) / 64, 256, (FIN * 128 + 64 * FIN) * sizeof(float)>>>(
        x, W1l, W1r, b1, n);
    k_agg1<<<(n * 16 + 255) / 256, 256>>>(n);

    // Layer 2
    k_gemm2<<<(n + 127) / 128, 128>>>(W2l, W2r, b2, n);
    k_agg2<<<(n + 255) / 256, 256>>>(out, n);
}